// round 2
// baseline (speedup 1.0000x reference)
#include <cuda_runtime.h>
#include <math.h>
#include <stdint.h>

// Problem constants
#define Bc   64
#define Tc   1024
#define Hc   256
#define NHc  4
#define DHc  64
#define ELc  768
#define TDc  256           // T - EL
#define QKVC 576           // (2*NH+1)*DH

// ---------------- scratch (device globals; no allocation allowed) -----------
__device__ float g_ceproj[Bc * Hc];
__device__ float g_buf1[Bc * Tc * Hc];          // 16.7M
__device__ float g_buf2[(size_t)Bc * Tc * QKVC];// 37.7M (also used as M x 512)
__device__ float g_buf3[Bc * Tc * Hc];          // 16.7M
__device__ float g_enr [Bc * Tc * Hc];          // 16.7M
__device__ float g_attn[Bc * NHc * TDc * DHc];  // 4.2M
__device__ float g_mattn[Bc * TDc * DHc];       // 1.05M
__device__ float g_da[Bc * TDc * Hc];
__device__ float g_d2[Bc * TDc * 2 * Hc];
__device__ float g_dx[Bc * TDc * Hc];
__device__ float g_dy[Bc * TDc * Hc];
__device__ float g_dz[Bc * TDc * Hc];

// ---------------- generic tiled SGEMM:  Y[M,N] = X[M,K] @ W[N,K]^T ----------
// act: 0 = none, 1 = ELU.  rowadd (optional): adds rowadd[(row>>10)*N + col].
// Requires: M % 64 == 0, N % 64 == 0, K % 16 == 0 (true for all calls here).
__global__ void gemm_k(const float* __restrict__ X, const float* __restrict__ W,
                       const float* __restrict__ bias, float* __restrict__ Y,
                       int M, int N, int K, int act,
                       const float* __restrict__ rowadd)
{
    __shared__ float Xs[16][64];
    __shared__ float Ws[16][64];

    const int tid  = threadIdx.x;
    const int tx   = tid & 15;
    const int ty   = tid >> 4;
    const int row0 = blockIdx.y << 6;
    const int col0 = blockIdx.x << 6;

    const int lm = tid >> 2;          // 0..63
    const int lk = (tid & 3) << 2;    // 0,4,8,12

    const float* Xp = X + (size_t)(row0 + lm) * K + lk;
    const float* Wp = W + (size_t)(col0 + lm) * K + lk;

    float acc[4][4] = {};

    for (int k0 = 0; k0 < K; k0 += 16) {
        float4 xv = *reinterpret_cast<const float4*>(Xp + k0);
        float4 wv = *reinterpret_cast<const float4*>(Wp + k0);
        Xs[lk + 0][lm] = xv.x; Xs[lk + 1][lm] = xv.y;
        Xs[lk + 2][lm] = xv.z; Xs[lk + 3][lm] = xv.w;
        Ws[lk + 0][lm] = wv.x; Ws[lk + 1][lm] = wv.y;
        Ws[lk + 2][lm] = wv.z; Ws[lk + 3][lm] = wv.w;
        __syncthreads();

        #pragma unroll
        for (int kk = 0; kk < 16; kk++) {
            float4 a4 = *reinterpret_cast<const float4*>(&Xs[kk][ty << 2]);
            float4 b4 = *reinterpret_cast<const float4*>(&Ws[kk][tx << 2]);
            float a[4] = {a4.x, a4.y, a4.z, a4.w};
            float b[4] = {b4.x, b4.y, b4.z, b4.w};
            #pragma unroll
            for (int i = 0; i < 4; i++)
                #pragma unroll
                for (int j = 0; j < 4; j++)
                    acc[i][j] = fmaf(a[i], b[j], acc[i][j]);
        }
        __syncthreads();
    }

    #pragma unroll
    for (int i = 0; i < 4; i++) {
        int row = row0 + (ty << 2) + i;
        #pragma unroll
        for (int j = 0; j < 4; j++) {
            int col = col0 + (tx << 2) + j;
            float v = acc[i][j];
            if (bias)   v += bias[col];
            if (rowadd) v += rowadd[(size_t)(row >> 10) * N + col];
            if (act == 1) v = v > 0.f ? v : expm1f(v);
            Y[(size_t)row * N + col] = v;
        }
    }
}

// ---------------- fused residual + LayerNorm (N = 256, 1 warp / row) --------
// decmap: 0 -> resid row = m ; 1 -> resid row = (m/TD)*T + EL + (m%TD)
__global__ void ln_k(const float* __restrict__ a, const float* __restrict__ resid,
                     const float* __restrict__ g, const float* __restrict__ b,
                     float* __restrict__ out, int rows, int decmap)
{
    int warp = blockIdx.x * (blockDim.x >> 5) + (threadIdx.x >> 5);
    if (warp >= rows) return;
    int lane = threadIdx.x & 31;

    size_t arow = (size_t)warp * Hc;
    size_t rrow;
    if (decmap) {
        int bb = warp / TDc, tl = warp % TDc;
        rrow = ((size_t)bb * Tc + ELc + tl) * Hc;
    } else {
        rrow = arow;
    }

    float vals[8];
    float s = 0.f, s2 = 0.f;
    #pragma unroll
    for (int i = 0; i < 8; i++) {
        int c = lane + 32 * i;
        float v = a[arow + c] + resid[rrow + c];
        vals[i] = v; s += v; s2 += v * v;
    }
    #pragma unroll
    for (int off = 16; off; off >>= 1) {
        s  += __shfl_xor_sync(0xffffffffu, s,  off);
        s2 += __shfl_xor_sync(0xffffffffu, s2, off);
    }
    float mu  = s  * (1.f / Hc);
    float var = s2 * (1.f / Hc) - mu * mu;
    float inv = rsqrtf(var + 1e-3f);
    #pragma unroll
    for (int i = 0; i < 8; i++) {
        int c = lane + 32 * i;
        out[arow + c] = (vals[i] - mu) * inv * g[c] + b[c];
    }
}

// ---------------- GLU: out[m,c] = y[m,c] * sigmoid(y[m,c+256]) (y ld = 512) -
__global__ void glu_k(const float* __restrict__ y, float* __restrict__ out, int rows)
{
    int idx = blockIdx.x * blockDim.x + threadIdx.x;
    if (idx >= rows * Hc) return;
    int r = idx >> 8, c = idx & 255;
    float av = y[(size_t)r * 512 + c];
    float gv = y[(size_t)r * 512 + 256 + c];
    out[idx] = av / (1.f + expf(-gv));
}

// ---------------- flash attention (queries t in [EL, T) only) ---------------
// qkv: (B*T, 576); q cols [h*64,h*64+64), k cols [256+h*64, ...), v cols [512,576)
// writes g_attn[(b,h,tl,d)]
__global__ void attn_k(const float* __restrict__ qkv)
{
    __shared__ float Qs[64][64];   // [d][i]   (Q^T)
    __shared__ float KPs[64][64];  // K^T, then reused for P
    __shared__ float Vs[64][64];   // [s][c]

    const int b = blockIdx.z, h = blockIdx.y, qt = blockIdx.x;
    const int t0 = ELc + (qt << 6);
    const int tid = threadIdx.x;
    const int tx = tid & 15, ty = tid >> 4;
    const int li  = tid >> 2;          // 0..63
    const int ld0 = (tid & 3) << 4;    // 0,16,32,48

    const float* qbase = qkv + ((size_t)b * Tc + t0) * QKVC + h * DHc;
    #pragma unroll
    for (int r = 0; r < 4; r++) {
        float4 v = *reinterpret_cast<const float4*>(qbase + (size_t)li * QKVC + ld0 + 4 * r);
        Qs[ld0 + 4*r + 0][li] = v.x; Qs[ld0 + 4*r + 1][li] = v.y;
        Qs[ld0 + 4*r + 2][li] = v.z; Qs[ld0 + 4*r + 3][li] = v.w;
    }

    float m_i[4], l_i[4], o[4][4];
    #pragma unroll
    for (int i = 0; i < 4; i++) {
        m_i[i] = -INFINITY; l_i[i] = 0.f;
        #pragma unroll
        for (int j = 0; j < 4; j++) o[i][j] = 0.f;
    }

    const int nkv = (t0 >> 6) + 1;
    const float* kbaseH = qkv + (size_t)b * Tc * QKVC + NHc * DHc + h * DHc;
    const float* vbase  = qkv + (size_t)b * Tc * QKVC + 2 * NHc * DHc;

    for (int kt = 0; kt < nkv; kt++) {
        const int s0 = kt << 6;
        __syncthreads();   // prior-iter reads of KPs/Vs done; also covers Q store

        const float* kb = kbaseH + (size_t)s0 * QKVC;
        const float* vb = vbase  + (size_t)s0 * QKVC;
        #pragma unroll
        for (int r = 0; r < 4; r++) {
            float4 kv4 = *reinterpret_cast<const float4*>(kb + (size_t)li * QKVC + ld0 + 4 * r);
            KPs[ld0 + 4*r + 0][li] = kv4.x; KPs[ld0 + 4*r + 1][li] = kv4.y;
            KPs[ld0 + 4*r + 2][li] = kv4.z; KPs[ld0 + 4*r + 3][li] = kv4.w;
            float4 vv4 = *reinterpret_cast<const float4*>(vb + (size_t)li * QKVC + ld0 + 4 * r);
            *reinterpret_cast<float4*>(&Vs[li][ld0 + 4 * r]) = vv4;
        }
        __syncthreads();

        // S = Q @ K^T  (per-thread 4x4)
        float s[4][4] = {};
        #pragma unroll
        for (int d = 0; d < 64; d++) {
            float4 qa  = *reinterpret_cast<const float4*>(&Qs[d][ty << 2]);
            float4 kb4 = *reinterpret_cast<const float4*>(&KPs[d][tx << 2]);
            float qa_[4] = {qa.x, qa.y, qa.z, qa.w};
            float kb_[4] = {kb4.x, kb4.y, kb4.z, kb4.w};
            #pragma unroll
            for (int i = 0; i < 4; i++)
                #pragma unroll
                for (int j = 0; j < 4; j++)
                    s[i][j] = fmaf(qa_[i], kb_[j], s[i][j]);
        }

        const bool diag = (s0 == t0);   // s0 <= t0 always; only diag tile masked
        #pragma unroll
        for (int i = 0; i < 4; i++)
            #pragma unroll
            for (int j = 0; j < 4; j++) {
                float sv = s[i][j] * 0.125f;
                if (diag && (s0 + (tx << 2) + j > t0 + (ty << 2) + i)) sv = -INFINITY;
                s[i][j] = sv;
            }

        float mnew[4];
        #pragma unroll
        for (int i = 0; i < 4; i++) {
            float rm = fmaxf(fmaxf(s[i][0], s[i][1]), fmaxf(s[i][2], s[i][3]));
            #pragma unroll
            for (int off = 1; off < 16; off <<= 1)
                rm = fmaxf(rm, __shfl_xor_sync(0xffffffffu, rm, off, 16));
            mnew[i] = fmaxf(m_i[i], rm);
        }
        #pragma unroll
        for (int i = 0; i < 4; i++)
            #pragma unroll
            for (int j = 0; j < 4; j++)
                s[i][j] = expf(s[i][j] - mnew[i]);
        #pragma unroll
        for (int i = 0; i < 4; i++) {
            float r_ = s[i][0] + s[i][1] + s[i][2] + s[i][3];
            #pragma unroll
            for (int off = 1; off < 16; off <<= 1)
                r_ += __shfl_xor_sync(0xffffffffu, r_, off, 16);
            float alpha = expf(m_i[i] - mnew[i]);
            l_i[i] = l_i[i] * alpha + r_;
            m_i[i] = mnew[i];
            #pragma unroll
            for (int j = 0; j < 4; j++) o[i][j] *= alpha;
        }

        __syncthreads();                       // done reading KPs as K
        #pragma unroll
        for (int i = 0; i < 4; i++)
            #pragma unroll
            for (int j = 0; j < 4; j++)
                KPs[(ty << 2) + i][(tx << 2) + j] = s[i][j];
        __syncthreads();

        // O += P @ V
        #pragma unroll 8
        for (int j = 0; j < 64; j++) {
            float4 vv = *reinterpret_cast<const float4*>(&Vs[j][tx << 2]);
            float vr[4] = {vv.x, vv.y, vv.z, vv.w};
            float p0 = KPs[(ty << 2) + 0][j];
            float p1 = KPs[(ty << 2) + 1][j];
            float p2 = KPs[(ty << 2) + 2][j];
            float p3 = KPs[(ty << 2) + 3][j];
            #pragma unroll
            for (int c = 0; c < 4; c++) {
                o[0][c] = fmaf(p0, vr[c], o[0][c]);
                o[1][c] = fmaf(p1, vr[c], o[1][c]);
                o[2][c] = fmaf(p2, vr[c], o[2][c]);
                o[3][c] = fmaf(p3, vr[c], o[3][c]);
            }
        }
    }

    #pragma unroll
    for (int i = 0; i < 4; i++) {
        float invl = 1.f / l_i[i];
        int tl = (qt << 6) + (ty << 2) + i;
        size_t base = (((size_t)b * NHc + h) * TDc + tl) * DHc + (tx << 2);
        #pragma unroll
        for (int j = 0; j < 4; j++)
            g_attn[base + j] = o[i][j] * invl;
    }
}

// ---------------- mean over heads -------------------------------------------
__global__ void mean_k()
{
    int idx = blockIdx.x * blockDim.x + threadIdx.x;
    if (idx >= Bc * TDc * DHc) return;
    int b = idx / (TDc * DHc);
    int rem = idx % (TDc * DHc);
    float s = 0.f;
    #pragma unroll
    for (int h = 0; h < NHc; h++)
        s += g_attn[((size_t)(b * NHc + h) * TDc * DHc) + rem];
    g_mattn[idx] = s * 0.25f;
}

// ---------------- host orchestration ----------------------------------------
extern "C" void kernel_launch(void* const* d_in, const int* in_sizes, int n_in,
                              void* d_out, int out_size)
{
    const float* TF       = (const float*)d_in[0];
    const float* ce       = (const float*)d_in[1];
    const float* eg_Wa    = (const float*)d_in[2];
    const float* eg_ba    = (const float*)d_in[3];
    const float* eg_Wc    = (const float*)d_in[4];
    const float* eg_Wi    = (const float*)d_in[5];
    const float* eg_bi    = (const float*)d_in[6];
    const float* eg_Wg    = (const float*)d_in[7];
    const float* eg_bg    = (const float*)d_in[8];
    const float* eg_lng   = (const float*)d_in[9];
    const float* eg_lnb   = (const float*)d_in[10];
    const float* att_Wqkv = (const float*)d_in[11];
    const float* att_Wout = (const float*)d_in[12];
    const float* ag_W     = (const float*)d_in[13];
    const float* ag_b     = (const float*)d_in[14];
    const float* aln_g    = (const float*)d_in[15];
    const float* aln_b    = (const float*)d_in[16];
    const float* pg_Wa    = (const float*)d_in[17];
    const float* pg_ba    = (const float*)d_in[18];
    const float* pg_Wi    = (const float*)d_in[19];
    const float* pg_bi    = (const float*)d_in[20];
    const float* pg_Wg    = (const float*)d_in[21];
    const float* pg_bg    = (const float*)d_in[22];
    const float* pg_lng   = (const float*)d_in[23];
    const float* pg_lnb   = (const float*)d_in[24];
    const float* dg_W     = (const float*)d_in[25];
    const float* dg_b     = (const float*)d_in[26];
    const float* dln_g    = (const float*)d_in[27];
    const float* dln_b    = (const float*)d_in[28];

    float *ceproj, *buf1, *buf2, *buf3, *enr, *mattn, *da, *d2, *dx, *dy, *dz;
    cudaGetSymbolAddress((void**)&ceproj, g_ceproj);
    cudaGetSymbolAddress((void**)&buf1,   g_buf1);
    cudaGetSymbolAddress((void**)&buf2,   g_buf2);
    cudaGetSymbolAddress((void**)&buf3,   g_buf3);
    cudaGetSymbolAddress((void**)&enr,    g_enr);
    cudaGetSymbolAddress((void**)&mattn,  g_mattn);
    cudaGetSymbolAddress((void**)&da,     g_da);
    cudaGetSymbolAddress((void**)&d2,     g_d2);
    cudaGetSymbolAddress((void**)&dx,     g_dx);
    cudaGetSymbolAddress((void**)&dy,     g_dy);
    cudaGetSymbolAddress((void**)&dz,     g_dz);

    const int Menc = Bc * Tc;     // 65536
    const int Mdec = Bc * TDc;    // 16384

    auto gemm = [&](const float* X, const float* W, const float* bias, float* Y,
                    int M, int N, int K, int act, const float* rowadd) {
        dim3 grid(N / 64, M / 64);
        gemm_k<<<grid, 256>>>(X, W, bias, Y, M, N, K, act, rowadd);
    };

    // --- encoder GLU block ---
    gemm(ce, eg_Wc, nullptr, ceproj, 64, Hc, Hc, 0, nullptr);
    gemm(TF, eg_Wa, eg_ba, buf1, Menc, Hc, Hc, 1, ceproj);          // elu(.. + ce proj)
    gemm(buf1, eg_Wi, eg_bi, buf3, Menc, Hc, Hc, 0, nullptr);
    gemm(buf3, eg_Wg, eg_bg, buf2, Menc, 2 * Hc, Hc, 0, nullptr);
    glu_k<<<Menc, 256>>>(buf2, buf1, Menc);
    ln_k<<<Menc / 8, 256>>>(buf1, TF, eg_lng, eg_lnb, enr, Menc, 0);

    // --- attention (decoder queries only) ---
    gemm(enr, att_Wqkv, nullptr, buf2, Menc, QKVC, Hc, 0, nullptr);
    attn_k<<<dim3(TDc / 64, NHc, Bc), 256>>>(buf2);
    mean_k<<<(Bc * TDc * DHc) / 256, 256>>>();
    gemm(mattn, att_Wout, nullptr, da, Mdec, Hc, DHc, 0, nullptr);

    // --- decoder ---
    gemm(da, ag_W, ag_b, d2, Mdec, 2 * Hc, Hc, 0, nullptr);
    glu_k<<<Mdec, 256>>>(d2, dx, Mdec);                              // gA
    ln_k<<<Mdec / 8, 256>>>(dx, enr, aln_g, aln_b, dy, Mdec, 1);     // xA

    gemm(dy, pg_Wa, pg_ba, dx, Mdec, Hc, Hc, 1, nullptr);            // elu
    gemm(dx, pg_Wi, pg_bi, dz, Mdec, Hc, Hc, 0, nullptr);
    gemm(dz, pg_Wg, pg_bg, d2, Mdec, 2 * Hc, Hc, 0, nullptr);
    glu_k<<<Mdec, 256>>>(d2, dx, Mdec);                              // gB
    ln_k<<<Mdec / 8, 256>>>(dx, dy, pg_lng, pg_lnb, dz, Mdec, 0);    // xB

    gemm(dz, dg_W, dg_b, d2, Mdec, 2 * Hc, Hc, 0, nullptr);
    glu_k<<<Mdec, 256>>>(d2, dx, Mdec);                              // gC
    ln_k<<<Mdec / 8, 256>>>(dx, TF, dln_g, dln_b, (float*)d_out, Mdec, 1);
}

// round 6
// speedup vs baseline: 1.7445x; 1.7445x over previous
#include <cuda_runtime.h>
#include <cuda_bf16.h>
#include <math.h>
#include <stdint.h>

// Problem constants
#define Bc   64
#define Tc   1024
#define Hc   256
#define NHc  4
#define DHc  64
#define ELc  768
#define TDc  256           // T - EL
#define QKVC 576           // (2*NH+1)*DH

// ---------------- scratch (device globals; no allocation allowed) -----------
__device__ float g_ceproj[Bc * Hc];
__device__ float g_buf1[Bc * Tc * Hc];
__device__ float g_buf2[(size_t)Bc * Tc * QKVC];
__device__ float g_buf3[Bc * Tc * Hc];
__device__ float g_enr [Bc * Tc * Hc];
__device__ float g_attn[Bc * NHc * TDc * DHc];
__device__ float g_mattn[Bc * TDc * DHc];
__device__ float g_da[Bc * TDc * Hc];
__device__ float g_d2[Bc * TDc * 2 * Hc];
__device__ float g_dx[Bc * TDc * Hc];
__device__ float g_dy[Bc * TDc * Hc];
__device__ float g_dz[Bc * TDc * Hc];

// ======================= helpers ============================================
__device__ __forceinline__ uint32_t smem_to_u32(const void* p) {
    uint32_t a;
    asm("{ .reg .u64 t; cvta.to.shared.u64 t, %1; cvt.u32.u64 %0, t; }"
        : "=r"(a) : "l"(p));
    return a;
}
#define SW128(o) ((o) ^ (((o) >> 3) & 0x70))

__device__ __forceinline__ uint32_t pack_bf16(float a, float b) {
    __nv_bfloat162 h = __floats2bfloat162_rn(a, b);
    return *reinterpret_cast<uint32_t*>(&h);
}

__device__ __forceinline__ void ldsm_x4(uint32_t& r0, uint32_t& r1,
                                        uint32_t& r2, uint32_t& r3, uint32_t a) {
    asm volatile("ldmatrix.sync.aligned.m8n8.x4.shared.b16 {%0,%1,%2,%3}, [%4];"
        : "=r"(r0), "=r"(r1), "=r"(r2), "=r"(r3) : "r"(a));
}
__device__ __forceinline__ void mma_bf16(float* c, const uint32_t* a, const uint32_t* b) {
    asm volatile(
        "mma.sync.aligned.m16n8k16.row.col.f32.bf16.bf16.f32 "
        "{%0,%1,%2,%3}, {%4,%5,%6,%7}, {%8,%9}, {%0,%1,%2,%3};"
        : "+f"(c[0]), "+f"(c[1]), "+f"(c[2]), "+f"(c[3])
        : "r"(a[0]), "r"(a[1]), "r"(a[2]), "r"(a[3]), "r"(b[0]), "r"(b[1]));
}

// ============ HMMA GEMM:  Y[M,N] = X[M,K] @ W[N,K]^T  =======================
// bf16 hi/lo split: Y = Xhi*Whi + Xhi*Wlo + Xlo*Whi (error ~2^-16).
// CTA tile 128x128, 8 warps (2x4), warp tile 64x32, K chunks of 64.
// act: 1 = ELU.  rowadd: adds rowadd[(row>>10)*N + col].
#define GS_A_HI 0
#define GS_A_LO 16384
#define GS_B_HI 32768
#define GS_B_LO 49152
#define GS_TOTAL 65536

__global__ void __launch_bounds__(256, 1)
mma_gemm_k(const float* __restrict__ X, const float* __restrict__ W,
           const float* __restrict__ bias, float* __restrict__ Y,
           int M, int N, int K, int act, const float* __restrict__ rowadd)
{
    extern __shared__ char smem[];
    const uint32_t sb = smem_to_u32(smem);
    const int tid = threadIdx.x;
    const int wid = tid >> 5, lane = tid & 31;
    const int warp_m = wid >> 2;       // 0..1
    const int warp_n = wid & 3;        // 0..3
    const int row0 = blockIdx.y << 7;
    const int col0 = blockIdx.x << 7;

    // load mapping: 8 threads per row, 4 row-groups; fully coalesced 256B rows
    const int ldr  = tid >> 3;          // 0..31
    const int ldc  = (tid & 7) << 3;    // 0,8,...,56

    float acc[4][4][4] = {};  // [mt][nt][reg]

    const int nchunks = K >> 6;
    for (int c = 0; c < nchunks; c++) {
        const int k0 = c << 6;
        if (c) __syncthreads();   // previous chunk's ldmatrix reads done

        #pragma unroll
        for (int g = 0; g < 4; g++) {
            const int lrow = ldr + (g << 5);            // 0..127
            const int arow = min(row0 + lrow, M - 1);
            const int brow = min(col0 + lrow, N - 1);
            const float* Ap = X + (size_t)arow * K + k0 + ldc;
            const float* Bp = W + (size_t)brow * K + k0 + ldc;
            #pragma unroll
            for (int h = 0; h < 2; h++) {
                const uint32_t off = SW128((uint32_t)(lrow * 128 + (ldc + h * 4) * 2));
                float4 av = *reinterpret_cast<const float4*>(Ap + h * 4);
                float a0 = __bfloat162float(__float2bfloat16(av.x));
                float a1 = __bfloat162float(__float2bfloat16(av.y));
                float a2 = __bfloat162float(__float2bfloat16(av.z));
                float a3 = __bfloat162float(__float2bfloat16(av.w));
                *reinterpret_cast<uint2*>(smem + GS_A_HI + off) =
                    make_uint2(pack_bf16(av.x, av.y), pack_bf16(av.z, av.w));
                *reinterpret_cast<uint2*>(smem + GS_A_LO + off) =
                    make_uint2(pack_bf16(av.x - a0, av.y - a1),
                               pack_bf16(av.z - a2, av.w - a3));

                float4 bv = *reinterpret_cast<const float4*>(Bp + h * 4);
                float b0 = __bfloat162float(__float2bfloat16(bv.x));
                float b1 = __bfloat162float(__float2bfloat16(bv.y));
                float b2 = __bfloat162float(__float2bfloat16(bv.z));
                float b3 = __bfloat162float(__float2bfloat16(bv.w));
                *reinterpret_cast<uint2*>(smem + GS_B_HI + off) =
                    make_uint2(pack_bf16(bv.x, bv.y), pack_bf16(bv.z, bv.w));
                *reinterpret_cast<uint2*>(smem + GS_B_LO + off) =
                    make_uint2(pack_bf16(bv.x - b0, bv.y - b1),
                               pack_bf16(bv.z - b2, bv.w - b3));
            }
        }
        __syncthreads();

        #pragma unroll
        for (int ks = 0; ks < 4; ks++) {
            const int kk = ks << 4;   // bf16 col base within 64

            uint32_t ah[4][4], al[4][4], bh[4][2], bl[4][2];
            {
                const int rr = (lane & 7) + ((lane >> 3) & 1) * 8;
                const int kc = kk + ((lane >> 4) << 3);
                #pragma unroll
                for (int mt = 0; mt < 4; mt++) {
                    const uint32_t off =
                        SW128((uint32_t)((warp_m * 64 + mt * 16 + rr) * 128 + kc * 2));
                    ldsm_x4(ah[mt][0], ah[mt][1], ah[mt][2], ah[mt][3],
                            sb + GS_A_HI + off);
                    ldsm_x4(al[mt][0], al[mt][1], al[mt][2], al[mt][3],
                            sb + GS_A_LO + off);
                }
            }
            {
                // B fragment: plain ldmatrix (NO trans) from [n][k] rows.
                // x4 matrices: lanes 0-7 -> n 0-7 @ k kk..kk+7  (b0, n-block 0)
                //              lanes 8-15 -> n 0-7 @ kk+8       (b1, n-block 0)
                //              lanes 16-23 -> n 8-15 @ kk       (b0, n-block 1)
                //              lanes 24-31 -> n 8-15 @ kk+8     (b1, n-block 1)
                const int nr = (lane & 7) + ((lane >> 4) << 3);
                const int kc = kk + ((lane >> 3) & 1) * 8;
                #pragma unroll
                for (int p = 0; p < 2; p++) {
                    const uint32_t off =
                        SW128((uint32_t)((warp_n * 32 + p * 16 + nr) * 128 + kc * 2));
                    uint32_t r0, r1, r2, r3;
                    ldsm_x4(r0, r1, r2, r3, sb + GS_B_HI + off);
                    bh[2*p][0] = r0; bh[2*p][1] = r1;
                    bh[2*p+1][0] = r2; bh[2*p+1][1] = r3;
                    ldsm_x4(r0, r1, r2, r3, sb + GS_B_LO + off);
                    bl[2*p][0] = r0; bl[2*p][1] = r1;
                    bl[2*p+1][0] = r2; bl[2*p+1][1] = r3;
                }
            }

            #pragma unroll
            for (int mt = 0; mt < 4; mt++)
                #pragma unroll
                for (int nt = 0; nt < 4; nt++) {
                    mma_bf16(acc[mt][nt], ah[mt], bh[nt]);
                    mma_bf16(acc[mt][nt], ah[mt], bl[nt]);
                    mma_bf16(acc[mt][nt], al[mt], bh[nt]);
                }
        }
    }

    // -------- epilogue: direct stores with fused bias/rowadd/ELU ------------
    const int r_hi  = lane >> 2;          // 0..7
    const int cpair = (lane & 3) << 1;    // 0,2,4,6

    #pragma unroll
    for (int mt = 0; mt < 4; mt++) {
        const int rbase = row0 + warp_m * 64 + mt * 16;
        #pragma unroll
        for (int h = 0; h < 2; h++) {
            const int grow = rbase + r_hi + h * 8;
            if (grow >= M) continue;
            #pragma unroll
            for (int nt = 0; nt < 4; nt++) {
                const int gcol = col0 + warp_n * 32 + nt * 8 + cpair;
                if (gcol >= N) continue;
                float v0 = acc[mt][nt][2 * h];
                float v1 = acc[mt][nt][2 * h + 1];
                if (bias) { v0 += bias[gcol]; v1 += bias[gcol + 1]; }
                if (rowadd) {
                    const size_t rb = (size_t)(grow >> 10) * N;
                    v0 += rowadd[rb + gcol];
                    v1 += rowadd[rb + gcol + 1];
                }
                if (act == 1) {
                    v0 = v0 > 0.f ? v0 : expm1f(v0);
                    v1 = v1 > 0.f ? v1 : expm1f(v1);
                }
                *reinterpret_cast<float2*>(Y + (size_t)grow * N + gcol) =
                    make_float2(v0, v1);
            }
        }
    }
}

// ---------------- fused residual + LayerNorm (N = 256, 1 warp / row) --------
__global__ void ln_k(const float* __restrict__ a, const float* __restrict__ resid,
                     const float* __restrict__ g, const float* __restrict__ b,
                     float* __restrict__ out, int rows, int decmap)
{
    int warp = blockIdx.x * (blockDim.x >> 5) + (threadIdx.x >> 5);
    if (warp >= rows) return;
    int lane = threadIdx.x & 31;

    size_t arow = (size_t)warp * Hc;
    size_t rrow;
    if (decmap) {
        int bb = warp / TDc, tl = warp % TDc;
        rrow = ((size_t)bb * Tc + ELc + tl) * Hc;
    } else {
        rrow = arow;
    }

    float vals[8];
    float s = 0.f, s2 = 0.f;
    #pragma unroll
    for (int i = 0; i < 8; i++) {
        int c = lane + 32 * i;
        float v = a[arow + c] + resid[rrow + c];
        vals[i] = v; s += v; s2 += v * v;
    }
    #pragma unroll
    for (int off = 16; off; off >>= 1) {
        s  += __shfl_xor_sync(0xffffffffu, s,  off);
        s2 += __shfl_xor_sync(0xffffffffu, s2, off);
    }
    float mu  = s  * (1.f / Hc);
    float var = s2 * (1.f / Hc) - mu * mu;
    float inv = rsqrtf(var + 1e-3f);
    #pragma unroll
    for (int i = 0; i < 8; i++) {
        int c = lane + 32 * i;
        out[arow + c] = (vals[i] - mu) * inv * g[c] + b[c];
    }
}

// ---------------- GLU: out[m,c] = y[m,c] * sigmoid(y[m,c+256]) (ld = 512) ---
__global__ void glu_k(const float* __restrict__ y, float* __restrict__ out, int rows)
{
    int idx = blockIdx.x * blockDim.x + threadIdx.x;
    if (idx >= rows * Hc) return;
    int r = idx >> 8, c = idx & 255;
    float av = y[(size_t)r * 512 + c];
    float gv = y[(size_t)r * 512 + 256 + c];
    out[idx] = av / (1.f + expf(-gv));
}

// ---------------- flash attention (queries t in [EL, T) only) ---------------
__global__ void attn_k(const float* __restrict__ qkv)
{
    __shared__ float Qs[64][64];
    __shared__ float KPs[64][64];
    __shared__ float Vs[64][64];

    const int b = blockIdx.z, h = blockIdx.y, qt = blockIdx.x;
    const int t0 = ELc + (qt << 6);
    const int tid = threadIdx.x;
    const int tx = tid & 15, ty = tid >> 4;
    const int li  = tid >> 2;
    const int ld0 = (tid & 3) << 4;

    const float* qbase = qkv + ((size_t)b * Tc + t0) * QKVC + h * DHc;
    #pragma unroll
    for (int r = 0; r < 4; r++) {
        float4 v = *reinterpret_cast<const float4*>(qbase + (size_t)li * QKVC + ld0 + 4 * r);
        Qs[ld0 + 4*r + 0][li] = v.x; Qs[ld0 + 4*r + 1][li] = v.y;
        Qs[ld0 + 4*r + 2][li] = v.z; Qs[ld0 + 4*r + 3][li] = v.w;
    }

    float m_i[4], l_i[4], o[4][4];
    #pragma unroll
    for (int i = 0; i < 4; i++) {
        m_i[i] = -INFINITY; l_i[i] = 0.f;
        #pragma unroll
        for (int j = 0; j < 4; j++) o[i][j] = 0.f;
    }

    const int nkv = (t0 >> 6) + 1;
    const float* kbaseH = qkv + (size_t)b * Tc * QKVC + NHc * DHc + h * DHc;
    const float* vbase  = qkv + (size_t)b * Tc * QKVC + 2 * NHc * DHc;

    for (int kt = 0; kt < nkv; kt++) {
        const int s0 = kt << 6;
        __syncthreads();

        const float* kb = kbaseH + (size_t)s0 * QKVC;
        const float* vb = vbase  + (size_t)s0 * QKVC;
        #pragma unroll
        for (int r = 0; r < 4; r++) {
            float4 kv4 = *reinterpret_cast<const float4*>(kb + (size_t)li * QKVC + ld0 + 4 * r);
            KPs[ld0 + 4*r + 0][li] = kv4.x; KPs[ld0 + 4*r + 1][li] = kv4.y;
            KPs[ld0 + 4*r + 2][li] = kv4.z; KPs[ld0 + 4*r + 3][li] = kv4.w;
            float4 vv4 = *reinterpret_cast<const float4*>(vb + (size_t)li * QKVC + ld0 + 4 * r);
            *reinterpret_cast<float4*>(&Vs[li][ld0 + 4 * r]) = vv4;
        }
        __syncthreads();

        float s[4][4] = {};
        #pragma unroll
        for (int d = 0; d < 64; d++) {
            float4 qa  = *reinterpret_cast<const float4*>(&Qs[d][ty << 2]);
            float4 kb4 = *reinterpret_cast<const float4*>(&KPs[d][tx << 2]);
            float qa_[4] = {qa.x, qa.y, qa.z, qa.w};
            float kb_[4] = {kb4.x, kb4.y, kb4.z, kb4.w};
            #pragma unroll
            for (int i = 0; i < 4; i++)
                #pragma unroll
                for (int j = 0; j < 4; j++)
                    s[i][j] = fmaf(qa_[i], kb_[j], s[i][j]);
        }

        const bool diag = (s0 == t0);
        #pragma unroll
        for (int i = 0; i < 4; i++)
            #pragma unroll
            for (int j = 0; j < 4; j++) {
                float sv = s[i][j] * 0.125f;
                if (diag && (s0 + (tx << 2) + j > t0 + (ty << 2) + i)) sv = -INFINITY;
                s[i][j] = sv;
            }

        float mnew[4];
        #pragma unroll
        for (int i = 0; i < 4; i++) {
            float rm = fmaxf(fmaxf(s[i][0], s[i][1]), fmaxf(s[i][2], s[i][3]));
            #pragma unroll
            for (int off = 1; off < 16; off <<= 1)
                rm = fmaxf(rm, __shfl_xor_sync(0xffffffffu, rm, off, 16));
            mnew[i] = fmaxf(m_i[i], rm);
        }
        #pragma unroll
        for (int i = 0; i < 4; i++)
            #pragma unroll
            for (int j = 0; j < 4; j++)
                s[i][j] = expf(s[i][j] - mnew[i]);
        #pragma unroll
        for (int i = 0; i < 4; i++) {
            float r_ = s[i][0] + s[i][1] + s[i][2] + s[i][3];
            #pragma unroll
            for (int off = 1; off < 16; off <<= 1)
                r_ += __shfl_xor_sync(0xffffffffu, r_, off, 16);
            float alpha = expf(m_i[i] - mnew[i]);
            l_i[i] = l_i[i] * alpha + r_;
            m_i[i] = mnew[i];
            #pragma unroll
            for (int j = 0; j < 4; j++) o[i][j] *= alpha;
        }

        __syncthreads();
        #pragma unroll
        for (int i = 0; i < 4; i++)
            #pragma unroll
            for (int j = 0; j < 4; j++)
                KPs[(ty << 2) + i][(tx << 2) + j] = s[i][j];
        __syncthreads();

        #pragma unroll 8
        for (int j = 0; j < 64; j++) {
            float4 vv = *reinterpret_cast<const float4*>(&Vs[j][tx << 2]);
            float vr[4] = {vv.x, vv.y, vv.z, vv.w};
            float p0 = KPs[(ty << 2) + 0][j];
            float p1 = KPs[(ty << 2) + 1][j];
            float p2 = KPs[(ty << 2) + 2][j];
            float p3 = KPs[(ty << 2) + 3][j];
            #pragma unroll
            for (int cidx = 0; cidx < 4; cidx++) {
                o[0][cidx] = fmaf(p0, vr[cidx], o[0][cidx]);
                o[1][cidx] = fmaf(p1, vr[cidx], o[1][cidx]);
                o[2][cidx] = fmaf(p2, vr[cidx], o[2][cidx]);
                o[3][cidx] = fmaf(p3, vr[cidx], o[3][cidx]);
            }
        }
    }

    #pragma unroll
    for (int i = 0; i < 4; i++) {
        float invl = 1.f / l_i[i];
        int tl = (qt << 6) + (ty << 2) + i;
        size_t base = (((size_t)b * NHc + h) * TDc + tl) * DHc + (tx << 2);
        #pragma unroll
        for (int j = 0; j < 4; j++)
            g_attn[base + j] = o[i][j] * invl;
    }
}

// ---------------- mean over heads -------------------------------------------
__global__ void mean_k()
{
    int idx = blockIdx.x * blockDim.x + threadIdx.x;
    if (idx >= Bc * TDc * DHc) return;
    int b = idx / (TDc * DHc);
    int rem = idx % (TDc * DHc);
    float s = 0.f;
    #pragma unroll
    for (int h = 0; h < NHc; h++)
        s += g_attn[((size_t)(b * NHc + h) * TDc * DHc) + rem];
    g_mattn[idx] = s * 0.25f;
}

// ---------------- host orchestration ----------------------------------------
extern "C" void kernel_launch(void* const* d_in, const int* in_sizes, int n_in,
                              void* d_out, int out_size)
{
    const float* TF       = (const float*)d_in[0];
    const float* ce       = (const float*)d_in[1];
    const float* eg_Wa    = (const float*)d_in[2];
    const float* eg_ba    = (const float*)d_in[3];
    const float* eg_Wc    = (const float*)d_in[4];
    const float* eg_Wi    = (const float*)d_in[5];
    const float* eg_bi    = (const float*)d_in[6];
    const float* eg_Wg    = (const float*)d_in[7];
    const float* eg_bg    = (const float*)d_in[8];
    const float* eg_lng   = (const float*)d_in[9];
    const float* eg_lnb   = (const float*)d_in[10];
    const float* att_Wqkv = (const float*)d_in[11];
    const float* att_Wout = (const float*)d_in[12];
    const float* ag_W     = (const float*)d_in[13];
    const float* ag_b     = (const float*)d_in[14];
    const float* aln_g    = (const float*)d_in[15];
    const float* aln_b    = (const float*)d_in[16];
    const float* pg_Wa    = (const float*)d_in[17];
    const float* pg_ba    = (const float*)d_in[18];
    const float* pg_Wi    = (const float*)d_in[19];
    const float* pg_bi    = (const float*)d_in[20];
    const float* pg_Wg    = (const float*)d_in[21];
    const float* pg_bg    = (const float*)d_in[22];
    const float* pg_lng   = (const float*)d_in[23];
    const float* pg_lnb   = (const float*)d_in[24];
    const float* dg_W     = (const float*)d_in[25];
    const float* dg_b     = (const float*)d_in[26];
    const float* dln_g    = (const float*)d_in[27];
    const float* dln_b    = (const float*)d_in[28];

    float *ceproj, *buf1, *buf2, *buf3, *enr, *mattn, *da, *d2, *dx, *dy, *dz;
    cudaGetSymbolAddress((void**)&ceproj, g_ceproj);
    cudaGetSymbolAddress((void**)&buf1,   g_buf1);
    cudaGetSymbolAddress((void**)&buf2,   g_buf2);
    cudaGetSymbolAddress((void**)&buf3,   g_buf3);
    cudaGetSymbolAddress((void**)&enr,    g_enr);
    cudaGetSymbolAddress((void**)&mattn,  g_mattn);
    cudaGetSymbolAddress((void**)&da,     g_da);
    cudaGetSymbolAddress((void**)&d2,     g_d2);
    cudaGetSymbolAddress((void**)&dx,     g_dx);
    cudaGetSymbolAddress((void**)&dy,     g_dy);
    cudaGetSymbolAddress((void**)&dz,     g_dz);

    static int attr_set = 0;
    if (!attr_set) {
        cudaFuncSetAttribute(mma_gemm_k, cudaFuncAttributeMaxDynamicSharedMemorySize,
                             GS_TOTAL);
        attr_set = 1;
    }

    const int Menc = Bc * Tc;     // 65536
    const int Mdec = Bc * TDc;    // 16384

    auto gemm = [&](const float* X, const float* W, const float* bias, float* Y,
                    int M, int N, int K, int act, const float* rowadd) {
        dim3 grid((N + 127) / 128, (M + 127) / 128);
        mma_gemm_k<<<grid, 256, GS_TOTAL>>>(X, W, bias, Y, M, N, K, act, rowadd);
    };

    // --- encoder GLU block ---
    gemm(ce, eg_Wc, nullptr, ceproj, 64, Hc, Hc, 0, nullptr);
    gemm(TF, eg_Wa, eg_ba, buf1, Menc, Hc, Hc, 1, ceproj);
    gemm(buf1, eg_Wi, eg_bi, buf3, Menc, Hc, Hc, 0, nullptr);
    gemm(buf3, eg_Wg, eg_bg, buf2, Menc, 2 * Hc, Hc, 0, nullptr);
    glu_k<<<Menc, 256>>>(buf2, buf1, Menc);
    ln_k<<<Menc / 8, 256>>>(buf1, TF, eg_lng, eg_lnb, enr, Menc, 0);

    // --- attention (decoder queries only) ---
    gemm(enr, att_Wqkv, nullptr, buf2, Menc, QKVC, Hc, 0, nullptr);
    attn_k<<<dim3(TDc / 64, NHc, Bc), 256>>>(buf2);
    mean_k<<<(Bc * TDc * DHc) / 256, 256>>>();
    gemm(mattn, att_Wout, nullptr, da, Mdec, Hc, DHc, 0, nullptr);

    // --- decoder ---
    gemm(da, ag_W, ag_b, d2, Mdec, 2 * Hc, Hc, 0, nullptr);
    glu_k<<<Mdec, 256>>>(d2, dx, Mdec);
    ln_k<<<Mdec / 8, 256>>>(dx, enr, aln_g, aln_b, dy, Mdec, 1);

    gemm(dy, pg_Wa, pg_ba, dx, Mdec, Hc, Hc, 1, nullptr);
    gemm(dx, pg_Wi, pg_bi, dz, Mdec, Hc, Hc, 0, nullptr);
    gemm(dz, pg_Wg, pg_bg, d2, Mdec, 2 * Hc, Hc, 0, nullptr);
    glu_k<<<Mdec, 256>>>(d2, dx, Mdec);
    ln_k<<<Mdec / 8, 256>>>(dx, dy, pg_lng, pg_lnb, dz, Mdec, 0);

    gemm(dz, dg_W, dg_b, d2, Mdec, 2 * Hc, Hc, 0, nullptr);
    glu_k<<<Mdec, 256>>>(d2, dx, Mdec);
    ln_k<<<Mdec / 8, 256>>>(dx, TF, dln_g, dln_b, (float*)d_out, Mdec, 1);
}

// round 7
// speedup vs baseline: 1.8386x; 1.0540x over previous
#include <cuda_runtime.h>
#include <cuda_bf16.h>
#include <math.h>
#include <stdint.h>

// Problem constants
#define Bc   64
#define Tc   1024
#define Hc   256
#define NHc  4
#define DHc  64
#define ELc  768
#define TDc  256           // T - EL
#define QKVC 576           // (2*NH+1)*DH

// ---------------- scratch (device globals; no allocation allowed) -----------
__device__ float g_ceproj[Bc * Hc];
__device__ float g_buf1[Bc * Tc * Hc];
__device__ float g_buf2[(size_t)Bc * Tc * QKVC];
__device__ float g_buf3[Bc * Tc * Hc];
__device__ float g_enr [Bc * Tc * Hc];
__device__ float g_attn[Bc * NHc * TDc * DHc];
__device__ float g_mattn[Bc * TDc * DHc];
__device__ float g_da[Bc * TDc * Hc];
__device__ float g_d2[Bc * TDc * 2 * Hc];
__device__ float g_dx[Bc * TDc * Hc];
__device__ float g_dy[Bc * TDc * Hc];
__device__ float g_dz[Bc * TDc * Hc];

// ======================= helpers ============================================
__device__ __forceinline__ uint32_t smem_to_u32(const void* p) {
    uint32_t a;
    asm("{ .reg .u64 t; cvta.to.shared.u64 t, %1; cvt.u32.u64 %0, t; }"
        : "=r"(a) : "l"(p));
    return a;
}
#define SW128(o) ((o) ^ (((o) >> 3) & 0x70))

__device__ __forceinline__ uint32_t pack_bf16(float a, float b) {
    __nv_bfloat162 h = __floats2bfloat162_rn(a, b);
    return *reinterpret_cast<uint32_t*>(&h);
}

__device__ __forceinline__ void ldsm_x4(uint32_t& r0, uint32_t& r1,
                                        uint32_t& r2, uint32_t& r3, uint32_t a) {
    asm volatile("ldmatrix.sync.aligned.m8n8.x4.shared.b16 {%0,%1,%2,%3}, [%4];"
        : "=r"(r0), "=r"(r1), "=r"(r2), "=r"(r3) : "r"(a));
}
__device__ __forceinline__ void mma_bf16(float* c, const uint32_t* a, const uint32_t* b) {
    asm volatile(
        "mma.sync.aligned.m16n8k16.row.col.f32.bf16.bf16.f32 "
        "{%0,%1,%2,%3}, {%4,%5,%6,%7}, {%8,%9}, {%0,%1,%2,%3};"
        : "+f"(c[0]), "+f"(c[1]), "+f"(c[2]), "+f"(c[3])
        : "r"(a[0]), "r"(a[1]), "r"(a[2]), "r"(a[3]), "r"(b[0]), "r"(b[1]));
}

// ============ HMMA GEMM:  Y[M,N] = X[M,K] @ W[N,K]^T  =======================
// bf16 hi/lo split: Y = Xhi*Whi + Xhi*Wlo + Xlo*Whi (error ~2^-16).
// CTA tile 128x64, 8 warps (2x4), warp tile 64x16, K chunks of 64.
// 2 CTAs/SM (48KB smem, <=128 regs) so one CTA's MMAs cover the other's loads.
// act: 1 = ELU.  rowadd: adds rowadd[(row>>10)*N + col].
#define GS_A_HI 0
#define GS_A_LO 16384
#define GS_B_HI 32768
#define GS_B_LO 40960
#define GS_TOTAL 49152

__global__ void __launch_bounds__(256, 2)
mma_gemm_k(const float* __restrict__ X, const float* __restrict__ W,
           const float* __restrict__ bias, float* __restrict__ Y,
           int M, int N, int K, int act, const float* __restrict__ rowadd)
{
    extern __shared__ char smem[];
    const uint32_t sb = smem_to_u32(smem);
    const int tid = threadIdx.x;
    const int wid = tid >> 5, lane = tid & 31;
    const int warp_m = wid >> 2;       // 0..1
    const int warp_n = wid & 3;        // 0..3
    const int row0 = blockIdx.y << 7;
    const int col0 = blockIdx.x << 6;  // 64-wide N tile

    // load mapping: 8 threads per row, row-groups of 32; coalesced 256B rows
    const int ldr  = tid >> 3;          // 0..31
    const int ldc  = (tid & 7) << 3;    // 0,8,...,56

    float acc[4][2][4] = {};  // [mt][nt][reg]

    const int nchunks = K >> 6;
    for (int c = 0; c < nchunks; c++) {
        const int k0 = c << 6;
        if (c) __syncthreads();   // previous chunk's ldmatrix reads done

        // ---- A tile: 128 rows --------------------------------------------
        #pragma unroll
        for (int g = 0; g < 4; g++) {
            const int lrow = ldr + (g << 5);            // 0..127
            const int arow = min(row0 + lrow, M - 1);
            const float* Ap = X + (size_t)arow * K + k0 + ldc;
            #pragma unroll
            for (int h = 0; h < 2; h++) {
                const uint32_t off = SW128((uint32_t)(lrow * 128 + (ldc + h * 4) * 2));
                float4 av = *reinterpret_cast<const float4*>(Ap + h * 4);
                float a0 = __bfloat162float(__float2bfloat16(av.x));
                float a1 = __bfloat162float(__float2bfloat16(av.y));
                float a2 = __bfloat162float(__float2bfloat16(av.z));
                float a3 = __bfloat162float(__float2bfloat16(av.w));
                *reinterpret_cast<uint2*>(smem + GS_A_HI + off) =
                    make_uint2(pack_bf16(av.x, av.y), pack_bf16(av.z, av.w));
                *reinterpret_cast<uint2*>(smem + GS_A_LO + off) =
                    make_uint2(pack_bf16(av.x - a0, av.y - a1),
                               pack_bf16(av.z - a2, av.w - a3));
            }
        }
        // ---- B tile: 64 rows ---------------------------------------------
        #pragma unroll
        for (int g = 0; g < 2; g++) {
            const int lrow = ldr + (g << 5);            // 0..63
            const int brow = min(col0 + lrow, N - 1);
            const float* Bp = W + (size_t)brow * K + k0 + ldc;
            #pragma unroll
            for (int h = 0; h < 2; h++) {
                const uint32_t off = SW128((uint32_t)(lrow * 128 + (ldc + h * 4) * 2));
                float4 bv = *reinterpret_cast<const float4*>(Bp + h * 4);
                float b0 = __bfloat162float(__float2bfloat16(bv.x));
                float b1 = __bfloat162float(__float2bfloat16(bv.y));
                float b2 = __bfloat162float(__float2bfloat16(bv.z));
                float b3 = __bfloat162float(__float2bfloat16(bv.w));
                *reinterpret_cast<uint2*>(smem + GS_B_HI + off) =
                    make_uint2(pack_bf16(bv.x, bv.y), pack_bf16(bv.z, bv.w));
                *reinterpret_cast<uint2*>(smem + GS_B_LO + off) =
                    make_uint2(pack_bf16(bv.x - b0, bv.y - b1),
                               pack_bf16(bv.z - b2, bv.w - b3));
            }
        }
        __syncthreads();

        #pragma unroll
        for (int ks = 0; ks < 4; ks++) {
            const int kk = ks << 4;   // bf16 col base within 64

            uint32_t ah[4][4], al[4][4], bh[2][2], bl[2][2];
            {
                const int rr = (lane & 7) + ((lane >> 3) & 1) * 8;
                const int kc = kk + ((lane >> 4) << 3);
                #pragma unroll
                for (int mt = 0; mt < 4; mt++) {
                    const uint32_t off =
                        SW128((uint32_t)((warp_m * 64 + mt * 16 + rr) * 128 + kc * 2));
                    ldsm_x4(ah[mt][0], ah[mt][1], ah[mt][2], ah[mt][3],
                            sb + GS_A_HI + off);
                    ldsm_x4(al[mt][0], al[mt][1], al[mt][2], al[mt][3],
                            sb + GS_A_LO + off);
                }
            }
            {
                // B fragment: plain ldmatrix (NO trans) from [n][k] rows.
                // x4: lanes 0-7 -> n 0-7 @ kk (b0, nt0); 8-15 -> n 0-7 @ kk+8 (b1, nt0)
                //     16-23 -> n 8-15 @ kk (b0, nt1);    24-31 -> n 8-15 @ kk+8 (b1, nt1)
                const int nr = (lane & 7) + ((lane >> 4) << 3);
                const int kc = kk + ((lane >> 3) & 1) * 8;
                const uint32_t off =
                    SW128((uint32_t)((warp_n * 16 + nr) * 128 + kc * 2));
                uint32_t r0, r1, r2, r3;
                ldsm_x4(r0, r1, r2, r3, sb + GS_B_HI + off);
                bh[0][0] = r0; bh[0][1] = r1; bh[1][0] = r2; bh[1][1] = r3;
                ldsm_x4(r0, r1, r2, r3, sb + GS_B_LO + off);
                bl[0][0] = r0; bl[0][1] = r1; bl[1][0] = r2; bl[1][1] = r3;
            }

            #pragma unroll
            for (int mt = 0; mt < 4; mt++)
                #pragma unroll
                for (int nt = 0; nt < 2; nt++) {
                    mma_bf16(acc[mt][nt], ah[mt], bh[nt]);
                    mma_bf16(acc[mt][nt], ah[mt], bl[nt]);
                    mma_bf16(acc[mt][nt], al[mt], bh[nt]);
                }
        }
    }

    // -------- epilogue: direct stores with fused bias/rowadd/ELU ------------
    const int r_hi  = lane >> 2;          // 0..7
    const int cpair = (lane & 3) << 1;    // 0,2,4,6

    #pragma unroll
    for (int mt = 0; mt < 4; mt++) {
        const int rbase = row0 + warp_m * 64 + mt * 16;
        #pragma unroll
        for (int h = 0; h < 2; h++) {
            const int grow = rbase + r_hi + h * 8;
            if (grow >= M) continue;
            #pragma unroll
            for (int nt = 0; nt < 2; nt++) {
                const int gcol = col0 + warp_n * 16 + nt * 8 + cpair;
                if (gcol >= N) continue;
                float v0 = acc[mt][nt][2 * h];
                float v1 = acc[mt][nt][2 * h + 1];
                if (bias) { v0 += bias[gcol]; v1 += bias[gcol + 1]; }
                if (rowadd) {
                    const size_t rb = (size_t)(grow >> 10) * N;
                    v0 += rowadd[rb + gcol];
                    v1 += rowadd[rb + gcol + 1];
                }
                if (act == 1) {
                    v0 = v0 > 0.f ? v0 : expm1f(v0);
                    v1 = v1 > 0.f ? v1 : expm1f(v1);
                }
                *reinterpret_cast<float2*>(Y + (size_t)grow * N + gcol) =
                    make_float2(v0, v1);
            }
        }
    }
}

// ---------------- fused residual + LayerNorm (N = 256, 1 warp / row) --------
__global__ void ln_k(const float* __restrict__ a, const float* __restrict__ resid,
                     const float* __restrict__ g, const float* __restrict__ b,
                     float* __restrict__ out, int rows, int decmap)
{
    int warp = blockIdx.x * (blockDim.x >> 5) + (threadIdx.x >> 5);
    if (warp >= rows) return;
    int lane = threadIdx.x & 31;

    size_t arow = (size_t)warp * Hc;
    size_t rrow;
    if (decmap) {
        int bb = warp / TDc, tl = warp % TDc;
        rrow = ((size_t)bb * Tc + ELc + tl) * Hc;
    } else {
        rrow = arow;
    }

    float vals[8];
    float s = 0.f, s2 = 0.f;
    #pragma unroll
    for (int i = 0; i < 8; i++) {
        int c = lane + 32 * i;
        float v = a[arow + c] + resid[rrow + c];
        vals[i] = v; s += v; s2 += v * v;
    }
    #pragma unroll
    for (int off = 16; off; off >>= 1) {
        s  += __shfl_xor_sync(0xffffffffu, s,  off);
        s2 += __shfl_xor_sync(0xffffffffu, s2, off);
    }
    float mu  = s  * (1.f / Hc);
    float var = s2 * (1.f / Hc) - mu * mu;
    float inv = rsqrtf(var + 1e-3f);
    #pragma unroll
    for (int i = 0; i < 8; i++) {
        int c = lane + 32 * i;
        out[arow + c] = (vals[i] - mu) * inv * g[c] + b[c];
    }
}

// ---------------- GLU: out[m,c] = y[m,c] * sigmoid(y[m,c+256]) (ld = 512) ---
__global__ void glu_k(const float* __restrict__ y, float* __restrict__ out, int rows)
{
    int idx = blockIdx.x * blockDim.x + threadIdx.x;
    if (idx >= rows * Hc) return;
    int r = idx >> 8, c = idx & 255;
    float av = y[(size_t)r * 512 + c];
    float gv = y[(size_t)r * 512 + 256 + c];
    out[idx] = av / (1.f + expf(-gv));
}

// ---------------- flash attention (queries t in [EL, T) only) ---------------
__global__ void attn_k(const float* __restrict__ qkv)
{
    __shared__ float Qs[64][64];
    __shared__ float KPs[64][64];
    __shared__ float Vs[64][64];

    const int b = blockIdx.z, h = blockIdx.y, qt = blockIdx.x;
    const int t0 = ELc + (qt << 6);
    const int tid = threadIdx.x;
    const int tx = tid & 15, ty = tid >> 4;
    const int li  = tid >> 2;
    const int ld0 = (tid & 3) << 4;

    const float* qbase = qkv + ((size_t)b * Tc + t0) * QKVC + h * DHc;
    #pragma unroll
    for (int r = 0; r < 4; r++) {
        float4 v = *reinterpret_cast<const float4*>(qbase + (size_t)li * QKVC + ld0 + 4 * r);
        Qs[ld0 + 4*r + 0][li] = v.x; Qs[ld0 + 4*r + 1][li] = v.y;
        Qs[ld0 + 4*r + 2][li] = v.z; Qs[ld0 + 4*r + 3][li] = v.w;
    }

    float m_i[4], l_i[4], o[4][4];
    #pragma unroll
    for (int i = 0; i < 4; i++) {
        m_i[i] = -INFINITY; l_i[i] = 0.f;
        #pragma unroll
        for (int j = 0; j < 4; j++) o[i][j] = 0.f;
    }

    const int nkv = (t0 >> 6) + 1;
    const float* kbaseH = qkv + (size_t)b * Tc * QKVC + NHc * DHc + h * DHc;
    const float* vbase  = qkv + (size_t)b * Tc * QKVC + 2 * NHc * DHc;

    for (int kt = 0; kt < nkv; kt++) {
        const int s0 = kt << 6;
        __syncthreads();

        const float* kb = kbaseH + (size_t)s0 * QKVC;
        const float* vb = vbase  + (size_t)s0 * QKVC;
        #pragma unroll
        for (int r = 0; r < 4; r++) {
            float4 kv4 = *reinterpret_cast<const float4*>(kb + (size_t)li * QKVC + ld0 + 4 * r);
            KPs[ld0 + 4*r + 0][li] = kv4.x; KPs[ld0 + 4*r + 1][li] = kv4.y;
            KPs[ld0 + 4*r + 2][li] = kv4.z; KPs[ld0 + 4*r + 3][li] = kv4.w;
            float4 vv4 = *reinterpret_cast<const float4*>(vb + (size_t)li * QKVC + ld0 + 4 * r);
            *reinterpret_cast<float4*>(&Vs[li][ld0 + 4 * r]) = vv4;
        }
        __syncthreads();

        float s[4][4] = {};
        #pragma unroll
        for (int d = 0; d < 64; d++) {
            float4 qa  = *reinterpret_cast<const float4*>(&Qs[d][ty << 2]);
            float4 kb4 = *reinterpret_cast<const float4*>(&KPs[d][tx << 2]);
            float qa_[4] = {qa.x, qa.y, qa.z, qa.w};
            float kb_[4] = {kb4.x, kb4.y, kb4.z, kb4.w};
            #pragma unroll
            for (int i = 0; i < 4; i++)
                #pragma unroll
                for (int j = 0; j < 4; j++)
                    s[i][j] = fmaf(qa_[i], kb_[j], s[i][j]);
        }

        const bool diag = (s0 == t0);
        #pragma unroll
        for (int i = 0; i < 4; i++)
            #pragma unroll
            for (int j = 0; j < 4; j++) {
                float sv = s[i][j] * 0.125f;
                if (diag && (s0 + (tx << 2) + j > t0 + (ty << 2) + i)) sv = -INFINITY;
                s[i][j] = sv;
            }

        float mnew[4];
        #pragma unroll
        for (int i = 0; i < 4; i++) {
            float rm = fmaxf(fmaxf(s[i][0], s[i][1]), fmaxf(s[i][2], s[i][3]));
            #pragma unroll
            for (int off = 1; off < 16; off <<= 1)
                rm = fmaxf(rm, __shfl_xor_sync(0xffffffffu, rm, off, 16));
            mnew[i] = fmaxf(m_i[i], rm);
        }
        #pragma unroll
        for (int i = 0; i < 4; i++)
            #pragma unroll
            for (int j = 0; j < 4; j++)
                s[i][j] = expf(s[i][j] - mnew[i]);
        #pragma unroll
        for (int i = 0; i < 4; i++) {
            float r_ = s[i][0] + s[i][1] + s[i][2] + s[i][3];
            #pragma unroll
            for (int off = 1; off < 16; off <<= 1)
                r_ += __shfl_xor_sync(0xffffffffu, r_, off, 16);
            float alpha = expf(m_i[i] - mnew[i]);
            l_i[i] = l_i[i] * alpha + r_;
            m_i[i] = mnew[i];
            #pragma unroll
            for (int j = 0; j < 4; j++) o[i][j] *= alpha;
        }

        __syncthreads();
        #pragma unroll
        for (int i = 0; i < 4; i++)
            #pragma unroll
            for (int j = 0; j < 4; j++)
                KPs[(ty << 2) + i][(tx << 2) + j] = s[i][j];
        __syncthreads();

        #pragma unroll 8
        for (int j = 0; j < 64; j++) {
            float4 vv = *reinterpret_cast<const float4*>(&Vs[j][tx << 2]);
            float vr[4] = {vv.x, vv.y, vv.z, vv.w};
            float p0 = KPs[(ty << 2) + 0][j];
            float p1 = KPs[(ty << 2) + 1][j];
            float p2 = KPs[(ty << 2) + 2][j];
            float p3 = KPs[(ty << 2) + 3][j];
            #pragma unroll
            for (int cidx = 0; cidx < 4; cidx++) {
                o[0][cidx] = fmaf(p0, vr[cidx], o[0][cidx]);
                o[1][cidx] = fmaf(p1, vr[cidx], o[1][cidx]);
                o[2][cidx] = fmaf(p2, vr[cidx], o[2][cidx]);
                o[3][cidx] = fmaf(p3, vr[cidx], o[3][cidx]);
            }
        }
    }

    #pragma unroll
    for (int i = 0; i < 4; i++) {
        float invl = 1.f / l_i[i];
        int tl = (qt << 6) + (ty << 2) + i;
        size_t base = (((size_t)b * NHc + h) * TDc + tl) * DHc + (tx << 2);
        #pragma unroll
        for (int j = 0; j < 4; j++)
            g_attn[base + j] = o[i][j] * invl;
    }
}

// ---------------- mean over heads -------------------------------------------
__global__ void mean_k()
{
    int idx = blockIdx.x * blockDim.x + threadIdx.x;
    if (idx >= Bc * TDc * DHc) return;
    int b = idx / (TDc * DHc);
    int rem = idx % (TDc * DHc);
    float s = 0.f;
    #pragma unroll
    for (int h = 0; h < NHc; h++)
        s += g_attn[((size_t)(b * NHc + h) * TDc * DHc) + rem];
    g_mattn[idx] = s * 0.25f;
}

// ---------------- host orchestration ----------------------------------------
extern "C" void kernel_launch(void* const* d_in, const int* in_sizes, int n_in,
                              void* d_out, int out_size)
{
    const float* TF       = (const float*)d_in[0];
    const float* ce       = (const float*)d_in[1];
    const float* eg_Wa    = (const float*)d_in[2];
    const float* eg_ba    = (const float*)d_in[3];
    const float* eg_Wc    = (const float*)d_in[4];
    const float* eg_Wi    = (const float*)d_in[5];
    const float* eg_bi    = (const float*)d_in[6];
    const float* eg_Wg    = (const float*)d_in[7];
    const float* eg_bg    = (const float*)d_in[8];
    const float* eg_lng   = (const float*)d_in[9];
    const float* eg_lnb   = (const float*)d_in[10];
    const float* att_Wqkv = (const float*)d_in[11];
    const float* att_Wout = (const float*)d_in[12];
    const float* ag_W     = (const float*)d_in[13];
    const float* ag_b     = (const float*)d_in[14];
    const float* aln_g    = (const float*)d_in[15];
    const float* aln_b    = (const float*)d_in[16];
    const float* pg_Wa    = (const float*)d_in[17];
    const float* pg_ba    = (const float*)d_in[18];
    const float* pg_Wi    = (const float*)d_in[19];
    const float* pg_bi    = (const float*)d_in[20];
    const float* pg_Wg    = (const float*)d_in[21];
    const float* pg_bg    = (const float*)d_in[22];
    const float* pg_lng   = (const float*)d_in[23];
    const float* pg_lnb   = (const float*)d_in[24];
    const float* dg_W     = (const float*)d_in[25];
    const float* dg_b     = (const float*)d_in[26];
    const float* dln_g    = (const float*)d_in[27];
    const float* dln_b    = (const float*)d_in[28];

    float *ceproj, *buf1, *buf2, *buf3, *enr, *mattn, *da, *d2, *dx, *dy, *dz;
    cudaGetSymbolAddress((void**)&ceproj, g_ceproj);
    cudaGetSymbolAddress((void**)&buf1,   g_buf1);
    cudaGetSymbolAddress((void**)&buf2,   g_buf2);
    cudaGetSymbolAddress((void**)&buf3,   g_buf3);
    cudaGetSymbolAddress((void**)&enr,    g_enr);
    cudaGetSymbolAddress((void**)&mattn,  g_mattn);
    cudaGetSymbolAddress((void**)&da,     g_da);
    cudaGetSymbolAddress((void**)&d2,     g_d2);
    cudaGetSymbolAddress((void**)&dx,     g_dx);
    cudaGetSymbolAddress((void**)&dy,     g_dy);
    cudaGetSymbolAddress((void**)&dz,     g_dz);

    static int attr_set = 0;
    if (!attr_set) {
        cudaFuncSetAttribute(mma_gemm_k, cudaFuncAttributeMaxDynamicSharedMemorySize,
                             GS_TOTAL);
        attr_set = 1;
    }

    const int Menc = Bc * Tc;     // 65536
    const int Mdec = Bc * TDc;    // 16384

    auto gemm = [&](const float* X, const float* W, const float* bias, float* Y,
                    int M, int N, int K, int act, const float* rowadd) {
        dim3 grid((N + 63) / 64, (M + 127) / 128);
        mma_gemm_k<<<grid, 256, GS_TOTAL>>>(X, W, bias, Y, M, N, K, act, rowadd);
    };

    // --- encoder GLU block ---
    gemm(ce, eg_Wc, nullptr, ceproj, 64, Hc, Hc, 0, nullptr);
    gemm(TF, eg_Wa, eg_ba, buf1, Menc, Hc, Hc, 1, ceproj);
    gemm(buf1, eg_Wi, eg_bi, buf3, Menc, Hc, Hc, 0, nullptr);
    gemm(buf3, eg_Wg, eg_bg, buf2, Menc, 2 * Hc, Hc, 0, nullptr);
    glu_k<<<Menc, 256>>>(buf2, buf1, Menc);
    ln_k<<<Menc / 8, 256>>>(buf1, TF, eg_lng, eg_lnb, enr, Menc, 0);

    // --- attention (decoder queries only) ---
    gemm(enr, att_Wqkv, nullptr, buf2, Menc, QKVC, Hc, 0, nullptr);
    attn_k<<<dim3(TDc / 64, NHc, Bc), 256>>>(buf2);
    mean_k<<<(Bc * TDc * DHc) / 256, 256>>>();
    gemm(mattn, att_Wout, nullptr, da, Mdec, Hc, DHc, 0, nullptr);

    // --- decoder ---
    gemm(da, ag_W, ag_b, d2, Mdec, 2 * Hc, Hc, 0, nullptr);
    glu_k<<<Mdec, 256>>>(d2, dx, Mdec);
    ln_k<<<Mdec / 8, 256>>>(dx, enr, aln_g, aln_b, dy, Mdec, 1);

    gemm(dy, pg_Wa, pg_ba, dx, Mdec, Hc, Hc, 1, nullptr);
    gemm(dx, pg_Wi, pg_bi, dz, Mdec, Hc, Hc, 0, nullptr);
    gemm(dz, pg_Wg, pg_bg, d2, Mdec, 2 * Hc, Hc, 0, nullptr);
    glu_k<<<Mdec, 256>>>(d2, dx, Mdec);
    ln_k<<<Mdec / 8, 256>>>(dx, dy, pg_lng, pg_lnb, dz, Mdec, 0);

    gemm(dz, dg_W, dg_b, d2, Mdec, 2 * Hc, Hc, 0, nullptr);
    glu_k<<<Mdec, 256>>>(d2, dx, Mdec);
    ln_k<<<Mdec / 8, 256>>>(dx, TF, dln_g, dln_b, (float*)d_out, Mdec, 1);
}